// round 16
// baseline (speedup 1.0000x reference)
#include <cuda_runtime.h>
#include <cuda_bf16.h>
#include <cuda_fp16.h>
#include <cstdint>

#define NODES 100000
#define EDGES 1600000
#define HID   128
#define BCAP  128                     // bucket capacity (P(deg>128) ~ 0)

// ---- scratch (static __device__; runtime alloc forbidden) ----
__device__ int    g_cnt[NODES];      // zero-init; k_dinv re-zeroes each run
__device__ int    g_deg[NODES];
__device__ float  g_dinv[NODES];
__device__ int    g_bucket[(size_t)NODES * BCAP];            // 51.2MB adjacency
__device__ __align__(16) __half g_xsh[(size_t)NODES * HID];  // raw x@W fp16
__device__ __align__(16) __nv_bfloat16 g_wh[128 * 128];      // W hi bf16 [k][n]
__device__ __align__(16) __nv_bfloat16 g_wl[128 * 128];      // W lo bf16

// ------------------------------------------------- W prep: bf16 hi/lo
__global__ void k_prep_w(const float* __restrict__ W) {
    int idx = blockIdx.x * blockDim.x + threadIdx.x;
    if (idx >= 128 * 128) return;
    float v = W[idx];
    __nv_bfloat16 hi = __float2bfloat16(v);
    g_wh[idx] = hi;
    g_wl[idx] = __float2bfloat16(v - __bfloat162float(hi));
}

// -------- per-warp dtype detect: lanes ballot over first 32 int64 values.
__device__ __forceinline__ int detect_is32(const void* ei, int N) {
    const long long* e64 = (const long long*)ei;
    int lane = threadIdx.x & 31;
    long long v = e64[lane];
    int bad = (v < 0 || v >= (long long)N) ? 1 : 0;
    unsigned m = __ballot_sync(0xffffffffu, bad);
    return m != 0u;
}

__device__ __forceinline__ int load_idx(const void* ei, size_t pos, int is32) {
    if (is32) return ((const int*)ei)[pos];
    return (int)((const long long*)ei)[pos];
}

// ------------------- single-pass bucket build, 2 edges/thread for MLP
__global__ void k_fill_bucket(const void* __restrict__ ei, int E) {
    int is32 = detect_is32(ei, NODES);
    int t = blockIdx.x * blockDim.x + threadIdx.x;
    int i0 = t * 2;
    if (i0 >= E) return;

    int s0 = load_idx(ei, i0, is32);
    int d0 = load_idx(ei, (size_t)E + i0, is32);
    int i1 = i0 + 1;
    if (i1 < E) {
        int s1 = load_idx(ei, i1, is32);
        int d1 = load_idx(ei, (size_t)E + i1, is32);
        int p0 = atomicAdd(&g_cnt[d0], 1);
        int p1 = atomicAdd(&g_cnt[d1], 1);
        if (p0 < BCAP) g_bucket[((size_t)d0 << 7) + p0] = s0;
        if (p1 < BCAP) g_bucket[((size_t)d1 << 7) + p1] = s1;
    } else {
        int p0 = atomicAdd(&g_cnt[d0], 1);
        if (p0 < BCAP) g_bucket[((size_t)d0 << 7) + p0] = s0;
    }
}

// ---------------------- cnt -> (deg, dinv), re-zero cnt for next replay
__global__ void k_dinv(int N) {
    int i = blockIdx.x * blockDim.x + threadIdx.x;
    if (i >= N) return;
    int c = g_cnt[i];
    g_deg[i] = c;
    g_cnt[i] = 0;
    g_dinv[i] = rsqrtf((float)(c + 1));    // +1 self loop
}

// =================================================================== GEMM
// xs = x @ W (raw fp16) via mma.sync m16n8k16 bf16x3.
// A fragments loaded DIRECTLY from global x (fp32) and hi/lo split in
// registers — no A smem, no convert stage. B (hi/lo) staged in smem once.
#define ST      136                   // B bf16 stride per row (272B)
#define BBYTES  (128 * ST * 2)        // 34816
#define SB_HI   0
#define SB_LO   BBYTES
#define SM_TOTAL (2 * BBYTES)         // 69632

__device__ __forceinline__ void ldsm4t(uint32_t& r0, uint32_t& r1, uint32_t& r2,
                                       uint32_t& r3, uint32_t addr) {
    asm volatile("ldmatrix.sync.aligned.m8n8.x4.trans.shared.b16 {%0,%1,%2,%3}, [%4];"
                 : "=r"(r0), "=r"(r1), "=r"(r2), "=r"(r3) : "r"(addr));
}
__device__ __forceinline__ void mma16816(float* c, const uint32_t* a, uint32_t b0,
                                         uint32_t b1) {
    asm volatile(
        "mma.sync.aligned.m16n8k16.row.col.f32.bf16.bf16.f32 "
        "{%0,%1,%2,%3}, {%4,%5,%6,%7}, {%8,%9}, {%0,%1,%2,%3};"
        : "+f"(c[0]), "+f"(c[1]), "+f"(c[2]), "+f"(c[3])
        : "r"(a[0]), "r"(a[1]), "r"(a[2]), "r"(a[3]), "r"(b0), "r"(b1));
}

// split a float2 into packed bf16x2 hi and lo
__device__ __forceinline__ void split2(float2 f, uint32_t& hi, uint32_t& lo) {
    __nv_bfloat16 h0 = __float2bfloat16(f.x);
    __nv_bfloat16 h1 = __float2bfloat16(f.y);
    __nv_bfloat16 l0 = __float2bfloat16(f.x - __bfloat162float(h0));
    __nv_bfloat16 l1 = __float2bfloat16(f.y - __bfloat162float(h1));
    __nv_bfloat162 hh = __halves2bfloat162(h0, h1);
    __nv_bfloat162 ll = __halves2bfloat162(l0, l1);
    hi = *(uint32_t*)&hh;
    lo = *(uint32_t*)&ll;
}

__global__ void __launch_bounds__(256) k_gemm(const float* __restrict__ x, int N) {
    extern __shared__ char smem[];
    uint32_t sb = (uint32_t)__cvta_generic_to_shared(smem);

    int tid = threadIdx.x;
    int wid = tid >> 5;
    int lane = tid & 31;
    int row0 = blockIdx.x * 128;

    // ---- stage B (W hi/lo) in smem, padded rows ----
    {
        const uint4* wh = (const uint4*)g_wh;
        const uint4* wl = (const uint4*)g_wl;
#pragma unroll
        for (int g = 0; g < 8; g++) {
            int i = tid + 256 * g;
            int r = i >> 4, c8 = i & 15;
            uint32_t off = r * (ST * 2) + c8 * 16;
            *(uint4*)(smem + SB_HI + off) = wh[i];
            *(uint4*)(smem + SB_LO + off) = wl[i];
        }
    }
    __syncthreads();

    int mg = wid >> 1;            // m-group: rows mg*32..+31
    int ng = wid & 1;             // n-group: cols ng*64..+63

    float c[2][8][4];
#pragma unroll
    for (int mi = 0; mi < 2; mi++)
#pragma unroll
        for (int n8 = 0; n8 < 8; n8++)
#pragma unroll
            for (int q = 0; q < 4; q++) c[mi][n8][q] = 0.f;

    int fr = lane >> 2;           // fragment row within m8 (0..7)
    int fc = (lane & 3) * 2;      // fragment col pair base (0,2,4,6)
    int b_k = (lane & 7) + ((lane >> 3) & 1) * 8;
    int b_n = ((lane >> 4) & 1) * 8;

    const float2 z2 = make_float2(0.f, 0.f);

#pragma unroll 2
    for (int ks = 0; ks < 8; ks++) {
        int k0 = ks * 16;

        // ---- A fragments direct from gmem, hi/lo split in regs ----
        uint32_t ah[2][4], al[2][4];
#pragma unroll
        for (int mi = 0; mi < 2; mi++) {
            int r_lo = row0 + mg * 32 + mi * 16 + fr;   // rows r, r+8
            int r_hi = r_lo + 8;
            const float* p0 = x + (size_t)r_lo * 128 + k0 + fc;
            const float* p1 = x + (size_t)r_hi * 128 + k0 + fc;
            float2 f0 = (r_lo < N) ? *(const float2*)(p0)     : z2;  // a0
            float2 f1 = (r_hi < N) ? *(const float2*)(p1)     : z2;  // a1
            float2 f2 = (r_lo < N) ? *(const float2*)(p0 + 8) : z2;  // a2
            float2 f3 = (r_hi < N) ? *(const float2*)(p1 + 8) : z2;  // a3
            split2(f0, ah[mi][0], al[mi][0]);
            split2(f1, ah[mi][1], al[mi][1]);
            split2(f2, ah[mi][2], al[mi][2]);
            split2(f3, ah[mi][3], al[mi][3]);
        }

        // ---- B fragments (hi and lo) once per ktile ----
        uint32_t bh[4][4], bl[4][4];
#pragma unroll
        for (int j = 0; j < 4; j++) {
            int n0 = ng * 64 + j * 16;
            uint32_t boff = (k0 + b_k) * (ST * 2) + (n0 + b_n) * 2;
            ldsm4t(bh[j][0], bh[j][1], bh[j][2], bh[j][3], sb + SB_HI + boff);
            ldsm4t(bl[j][0], bl[j][1], bl[j][2], bl[j][3], sb + SB_LO + boff);
        }

        // ---- 3 products: ah*bh + al*bh + ah*bl ----
#pragma unroll
        for (int mi = 0; mi < 2; mi++)
#pragma unroll
            for (int j = 0; j < 4; j++) {
                mma16816(c[mi][2 * j],     ah[mi], bh[j][0], bh[j][1]);
                mma16816(c[mi][2 * j + 1], ah[mi], bh[j][2], bh[j][3]);
                mma16816(c[mi][2 * j],     al[mi], bh[j][0], bh[j][1]);
                mma16816(c[mi][2 * j + 1], al[mi], bh[j][2], bh[j][3]);
                mma16816(c[mi][2 * j],     ah[mi], bl[j][0], bl[j][1]);
                mma16816(c[mi][2 * j + 1], ah[mi], bl[j][2], bl[j][3]);
            }
    }

    // ---- epilogue: store raw x@W fp16 ----
#pragma unroll
    for (int mi = 0; mi < 2; mi++) {
        int r0 = mg * 32 + mi * 16 + (lane >> 2);
        int r1 = r0 + 8;
        int gm0 = row0 + r0, gm1 = row0 + r1;
#pragma unroll
        for (int n8 = 0; n8 < 8; n8++) {
            int col = ng * 64 + n8 * 8 + (lane & 3) * 2;
            if (gm0 < N) {
                __half2 h = __floats2half2_rn(c[mi][n8][0], c[mi][n8][1]);
                *(__half2*)(g_xsh + (size_t)gm0 * 128 + col) = h;
            }
            if (gm1 < N) {
                __half2 h = __floats2half2_rn(c[mi][n8][2], c[mi][n8][3]);
                *(__half2*)(g_xsh + (size_t)gm1 * 128 + col) = h;
            }
        }
    }
}

// ---------------------------------------------- aggregation: one warp / node
__global__ void __launch_bounds__(256) k_agg(const float* __restrict__ b,
                                             float* __restrict__ out, int N) {
    int gw = (blockIdx.x * blockDim.x + threadIdx.x) >> 5;
    int lane = threadIdx.x & 31;
    if (gw >= N) return;

    const uint2* xsv = (const uint2*)g_xsh;   // 8B = 4 halves per lane
    float w_self = g_dinv[gw];

    float a0, a1, a2, a3;
    {
        uint2 v = xsv[(size_t)gw * 32 + lane];
        float2 f01 = __half22float2(*(__half2*)&v.x);
        float2 f23 = __half22float2(*(__half2*)&v.y);
        a0 = w_self * f01.x; a1 = w_self * f01.y;
        a2 = w_self * f23.x; a3 = w_self * f23.y;
    }
    float c0 = 0.f, c1 = 0.f, c2 = 0.f, c3 = 0.f;

    int deg = g_deg[gw];
    if (deg > BCAP) deg = BCAP;
    size_t base = (size_t)gw << 7;

    int i = 0;
    for (; i + 2 <= deg; i += 2) {
        int s0 = g_bucket[base + i];
        int s1 = g_bucket[base + i + 1];
        float w0 = g_dinv[s0];
        float w1 = g_dinv[s1];
        uint2 v0 = xsv[(size_t)s0 * 32 + lane];
        uint2 v1 = xsv[(size_t)s1 * 32 + lane];
        float2 p01 = __half22float2(*(__half2*)&v0.x);
        float2 p23 = __half22float2(*(__half2*)&v0.y);
        float2 q01 = __half22float2(*(__half2*)&v1.x);
        float2 q23 = __half22float2(*(__half2*)&v1.y);
        a0 = fmaf(w0, p01.x, a0); a1 = fmaf(w0, p01.y, a1);
        a2 = fmaf(w0, p23.x, a2); a3 = fmaf(w0, p23.y, a3);
        c0 = fmaf(w1, q01.x, c0); c1 = fmaf(w1, q01.y, c1);
        c2 = fmaf(w1, q23.x, c2); c3 = fmaf(w1, q23.y, c3);
    }
    if (i < deg) {
        int s0 = g_bucket[base + i];
        float w0 = g_dinv[s0];
        uint2 v0 = xsv[(size_t)s0 * 32 + lane];
        float2 p01 = __half22float2(*(__half2*)&v0.x);
        float2 p23 = __half22float2(*(__half2*)&v0.y);
        a0 = fmaf(w0, p01.x, a0); a1 = fmaf(w0, p01.y, a1);
        a2 = fmaf(w0, p23.x, a2); a3 = fmaf(w0, p23.y, a3);
    }
    a0 += c0; a1 += c1; a2 += c2; a3 += c3;

    float4 bb = ((const float4*)b)[lane];
    float4 o;
    o.x = fmaxf(fmaf(w_self, a0, bb.x), 0.f);
    o.y = fmaxf(fmaf(w_self, a1, bb.y), 0.f);
    o.z = fmaxf(fmaf(w_self, a2, bb.z), 0.f);
    o.w = fmaxf(fmaf(w_self, a3, bb.w), 0.f);
    ((float4*)out)[(size_t)gw * 32 + lane] = o;
}

// ---------------------------------------------------------------- launcher
extern "C" void kernel_launch(void* const* d_in, const int* in_sizes, int n_in,
                              void* d_out, int out_size) {
    const float* x  = (const float*)d_in[0];
    const void*  ei = d_in[1];                 // int32 or int64, auto-detected
    const float* W  = (const float*)d_in[2];
    const float* b  = (const float*)d_in[3];
    float* out      = (float*)d_out;

    int N = in_sizes[0] / HID;     // 100000
    int E = in_sizes[1] / 2;       // 1600000

    static cudaStream_t s1;
    static cudaEvent_t ev0, ev_gemm;
    static int inited = 0;
    if (!inited) {
        cudaFuncSetAttribute(k_gemm, cudaFuncAttributeMaxDynamicSharedMemorySize,
                             SM_TOTAL);
        cudaStreamCreateWithFlags(&s1, cudaStreamNonBlocking);
        cudaEventCreateWithFlags(&ev0, cudaEventDisableTiming);
        cudaEventCreateWithFlags(&ev_gemm, cudaEventDisableTiming);
        inited = 1;
    }

    // side stream: full GEMM chain (no dependencies on edge data)
    cudaEventRecord(ev0, 0);
    cudaStreamWaitEvent(s1, ev0, 0);
    k_prep_w<<<64, 256, 0, s1>>>(W);
    k_gemm<<<(N + 127) / 128, 256, SM_TOTAL, s1>>>(x, N);
    cudaEventRecord(ev_gemm, s1);

    // main chain: bucket build (detect inlined) -> dinv
    k_fill_bucket<<<(E / 2 + 255) / 256, 256>>>(ei, E);
    k_dinv<<<(N + 255) / 256, 256>>>(N);

    // join, aggregate
    cudaStreamWaitEvent(0, ev_gemm, 0);
    k_agg<<<(N * 32 + 255) / 256, 256>>>(b, out, N);
}

// round 17
// speedup vs baseline: 1.0333x; 1.0333x over previous
#include <cuda_runtime.h>
#include <cuda_bf16.h>
#include <cuda_fp16.h>
#include <cstdint>

#define NODES 100000
#define EDGES 1600000
#define HID   128
#define BCAP  128                     // bucket capacity (P(deg>128) ~ 0)

// ---- scratch (static __device__; runtime alloc forbidden) ----
__device__ int    g_cnt[NODES];      // zero-init; k_dinv re-zeroes each run
__device__ int    g_deg[NODES];
__device__ float  g_dinv[NODES];
__device__ int    g_bucket[(size_t)NODES * BCAP];            // 51.2MB adjacency
__device__ __align__(16) __half g_xsh[(size_t)NODES * HID];  // raw x@W fp16

// -------- per-warp dtype detect: lanes ballot over first 32 int64 values.
__device__ __forceinline__ int detect_is32(const void* ei, int N) {
    const long long* e64 = (const long long*)ei;
    int lane = threadIdx.x & 31;
    long long v = e64[lane];
    int bad = (v < 0 || v >= (long long)N) ? 1 : 0;
    unsigned m = __ballot_sync(0xffffffffu, bad);
    return m != 0u;
}

__device__ __forceinline__ int load_idx(const void* ei, size_t pos, int is32) {
    if (is32) return ((const int*)ei)[pos];
    return (int)((const long long*)ei)[pos];
}

// ------------------- single-pass bucket build, 2 edges/thread for MLP
__global__ void k_fill_bucket(const void* __restrict__ ei, int E) {
    int is32 = detect_is32(ei, NODES);
    int t = blockIdx.x * blockDim.x + threadIdx.x;
    int i0 = t * 2;
    if (i0 >= E) return;

    int s0 = load_idx(ei, i0, is32);
    int d0 = load_idx(ei, (size_t)E + i0, is32);
    int i1 = i0 + 1;
    if (i1 < E) {
        int s1 = load_idx(ei, i1, is32);
        int d1 = load_idx(ei, (size_t)E + i1, is32);
        int p0 = atomicAdd(&g_cnt[d0], 1);
        int p1 = atomicAdd(&g_cnt[d1], 1);
        if (p0 < BCAP) g_bucket[((size_t)d0 << 7) + p0] = s0;
        if (p1 < BCAP) g_bucket[((size_t)d1 << 7) + p1] = s1;
    } else {
        int p0 = atomicAdd(&g_cnt[d0], 1);
        if (p0 < BCAP) g_bucket[((size_t)d0 << 7) + p0] = s0;
    }
}

// ---------------------- cnt -> (deg, dinv), re-zero cnt for next replay
__global__ void k_dinv(int N) {
    int i = blockIdx.x * blockDim.x + threadIdx.x;
    if (i >= N) return;
    int c = g_cnt[i];
    g_deg[i] = c;
    g_cnt[i] = 0;
    g_dinv[i] = rsqrtf((float)(c + 1));    // +1 self loop
}

// =================================================================== GEMM
// xs = x @ W (raw fp16) via mma.sync m16n8k16 bf16x3 (hi/lo split).
// R15 monolith; W converted fp32->bf16 hi/lo IN-KERNEL (no prep pass).
#define ST      136                   // bf16 stride per row (conflict-free ldmatrix)
#define ABYTES  (128 * ST * 2)        // 34816 per array
#define SA_HI   0
#define SA_LO   (SA_HI + ABYTES)
#define SB_HI   (SA_LO + ABYTES)
#define SB_LO   (SB_HI + ABYTES)
#define SM_TOTAL (SB_LO + ABYTES)     // 139264

__device__ __forceinline__ void ldsm4(uint32_t& r0, uint32_t& r1, uint32_t& r2,
                                      uint32_t& r3, uint32_t addr) {
    asm volatile("ldmatrix.sync.aligned.m8n8.x4.shared.b16 {%0,%1,%2,%3}, [%4];"
                 : "=r"(r0), "=r"(r1), "=r"(r2), "=r"(r3) : "r"(addr));
}
__device__ __forceinline__ void ldsm4t(uint32_t& r0, uint32_t& r1, uint32_t& r2,
                                       uint32_t& r3, uint32_t addr) {
    asm volatile("ldmatrix.sync.aligned.m8n8.x4.trans.shared.b16 {%0,%1,%2,%3}, [%4];"
                 : "=r"(r0), "=r"(r1), "=r"(r2), "=r"(r3) : "r"(addr));
}
__device__ __forceinline__ void mma16816(float* c, const uint32_t* a, uint32_t b0,
                                         uint32_t b1) {
    asm volatile(
        "mma.sync.aligned.m16n8k16.row.col.f32.bf16.bf16.f32 "
        "{%0,%1,%2,%3}, {%4,%5,%6,%7}, {%8,%9}, {%0,%1,%2,%3};"
        : "+f"(c[0]), "+f"(c[1]), "+f"(c[2]), "+f"(c[3])
        : "r"(a[0]), "r"(a[1]), "r"(a[2]), "r"(a[3]), "r"(b0), "r"(b1));
}

__global__ void __launch_bounds__(256) k_gemm(const float* __restrict__ x,
                                              const float* __restrict__ W, int N) {
    extern __shared__ char smem[];
    uint32_t sb = (uint32_t)__cvta_generic_to_shared(smem);

    int tid = threadIdx.x;
    int wid = tid >> 5;
    int lane = tid & 31;
    int row0 = blockIdx.x * 128;

    // ---- convert W (fp32, L2-resident) -> bf16 hi/lo smem, padded rows ----
#pragma unroll
    for (int g = 0; g < 8; g++) {
        int i = tid + 256 * g;                 // (k row, 8-col group), 2048
        int r = i >> 4, c8 = i & 15;
        const float4* p = (const float4*)(W + (size_t)r * 128 + c8 * 8);
        float4 v0 = p[0], v1 = p[1];
        float f[8] = {v0.x, v0.y, v0.z, v0.w, v1.x, v1.y, v1.z, v1.w};
        alignas(16) __nv_bfloat16 hh[8];
        alignas(16) __nv_bfloat16 ll[8];
#pragma unroll
        for (int j = 0; j < 8; j++) {
            __nv_bfloat16 hi = __float2bfloat16(f[j]);
            hh[j] = hi;
            ll[j] = __float2bfloat16(f[j] - __bfloat162float(hi));
        }
        uint32_t off = r * (ST * 2) + c8 * 16;
        *(uint4*)(smem + SB_HI + off) = *(uint4*)hh;
        *(uint4*)(smem + SB_LO + off) = *(uint4*)ll;
    }

    // ---- convert x tile (128 x 128) fp32 -> bf16 hi/lo, padded rows ----
#pragma unroll
    for (int g = 0; g < 8; g++) {
        int i = tid + 256 * g;
        int m = i >> 4, c8 = i & 15;
        int gm = row0 + m;
        float4 v0 = make_float4(0.f, 0.f, 0.f, 0.f), v1 = v0;
        if (gm < N) {
            const float4* p = (const float4*)(x + (size_t)gm * 128 + c8 * 8);
            v0 = p[0]; v1 = p[1];
        }
        float f[8] = {v0.x, v0.y, v0.z, v0.w, v1.x, v1.y, v1.z, v1.w};
        alignas(16) __nv_bfloat16 hh[8];
        alignas(16) __nv_bfloat16 ll[8];
#pragma unroll
        for (int j = 0; j < 8; j++) {
            __nv_bfloat16 hi = __float2bfloat16(f[j]);
            hh[j] = hi;
            ll[j] = __float2bfloat16(f[j] - __bfloat162float(hi));
        }
        uint32_t off = m * (ST * 2) + c8 * 16;
        *(uint4*)(smem + SA_HI + off) = *(uint4*)hh;
        *(uint4*)(smem + SA_LO + off) = *(uint4*)ll;
    }
    __syncthreads();

    int mg = wid >> 1;            // m-group: rows mg*32..+31
    int ng = wid & 1;             // n-group: cols ng*64..+63

    float c[2][8][4];
#pragma unroll
    for (int mi = 0; mi < 2; mi++)
#pragma unroll
        for (int n8 = 0; n8 < 8; n8++)
#pragma unroll
            for (int q = 0; q < 4; q++) c[mi][n8][q] = 0.f;

    int a_row = (lane & 7) + ((lane >> 3) & 1) * 8;
    int a_k   = ((lane >> 4) & 1) * 8;
    int b_k   = (lane & 7) + ((lane >> 3) & 1) * 8;
    int b_n   = ((lane >> 4) & 1) * 8;

    const uint32_t aBase[3] = {sb + SA_HI, sb + SA_LO, sb + SA_HI};
    const uint32_t bBase[3] = {sb + SB_HI, sb + SB_HI, sb + SB_LO};

#pragma unroll
    for (int pass = 0; pass < 3; pass++) {
        uint32_t AB = aBase[pass], BB = bBase[pass];
#pragma unroll
        for (int ks = 0; ks < 8; ks++) {
            int k0 = ks * 16;
            uint32_t a[2][4];
#pragma unroll
            for (int mi = 0; mi < 2; mi++) {
                int r = mg * 32 + mi * 16 + a_row;
                ldsm4(a[mi][0], a[mi][1], a[mi][2], a[mi][3],
                      AB + r * (ST * 2) + (k0 + a_k) * 2);
            }
            uint32_t b[4][4];
#pragma unroll
            for (int j = 0; j < 4; j++) {
                int n0 = ng * 64 + j * 16;
                ldsm4t(b[j][0], b[j][1], b[j][2], b[j][3],
                       BB + (k0 + b_k) * (ST * 2) + (n0 + b_n) * 2);
            }
#pragma unroll
            for (int mi = 0; mi < 2; mi++)
#pragma unroll
                for (int j = 0; j < 4; j++) {
                    mma16816(c[mi][2 * j],     a[mi], b[j][0], b[j][1]);
                    mma16816(c[mi][2 * j + 1], a[mi], b[j][2], b[j][3]);
                }
        }
    }

    // ---- epilogue: store raw x@W fp16 ----
#pragma unroll
    for (int mi = 0; mi < 2; mi++) {
        int r0 = mg * 32 + mi * 16 + (lane >> 2);
        int r1 = r0 + 8;
        int gm0 = row0 + r0, gm1 = row0 + r1;
#pragma unroll
        for (int n8 = 0; n8 < 8; n8++) {
            int col = ng * 64 + n8 * 8 + (lane & 3) * 2;
            if (gm0 < N) {
                __half2 h = __floats2half2_rn(c[mi][n8][0], c[mi][n8][1]);
                *(__half2*)(g_xsh + (size_t)gm0 * 128 + col) = h;
            }
            if (gm1 < N) {
                __half2 h = __floats2half2_rn(c[mi][n8][2], c[mi][n8][3]);
                *(__half2*)(g_xsh + (size_t)gm1 * 128 + col) = h;
            }
        }
    }
}

// ---------------------------------------------- aggregation: one warp / node
// bucket adjacency, per-edge dinv[src] weight (broadcast 4B), fp32 accum.
__global__ void __launch_bounds__(256) k_agg(const float* __restrict__ b,
                                             float* __restrict__ out, int N) {
    int gw = (blockIdx.x * blockDim.x + threadIdx.x) >> 5;
    int lane = threadIdx.x & 31;
    if (gw >= N) return;

    const uint2* xsv = (const uint2*)g_xsh;   // 8B = 4 halves per lane
    float w_self = g_dinv[gw];

    float a0, a1, a2, a3;
    {
        uint2 v = xsv[(size_t)gw * 32 + lane];
        float2 f01 = __half22float2(*(__half2*)&v.x);
        float2 f23 = __half22float2(*(__half2*)&v.y);
        a0 = w_self * f01.x; a1 = w_self * f01.y;
        a2 = w_self * f23.x; a3 = w_self * f23.y;
    }
    float c0 = 0.f, c1 = 0.f, c2 = 0.f, c3 = 0.f;

    int deg = g_deg[gw];
    if (deg > BCAP) deg = BCAP;
    size_t base = (size_t)gw << 7;

    int i = 0;
    for (; i + 2 <= deg; i += 2) {
        int s0 = g_bucket[base + i];
        int s1 = g_bucket[base + i + 1];
        float w0 = g_dinv[s0];
        float w1 = g_dinv[s1];
        uint2 v0 = xsv[(size_t)s0 * 32 + lane];
        uint2 v1 = xsv[(size_t)s1 * 32 + lane];
        float2 p01 = __half22float2(*(__half2*)&v0.x);
        float2 p23 = __half22float2(*(__half2*)&v0.y);
        float2 q01 = __half22float2(*(__half2*)&v1.x);
        float2 q23 = __half22float2(*(__half2*)&v1.y);
        a0 = fmaf(w0, p01.x, a0); a1 = fmaf(w0, p01.y, a1);
        a2 = fmaf(w0, p23.x, a2); a3 = fmaf(w0, p23.y, a3);
        c0 = fmaf(w1, q01.x, c0); c1 = fmaf(w1, q01.y, c1);
        c2 = fmaf(w1, q23.x, c2); c3 = fmaf(w1, q23.y, c3);
    }
    if (i < deg) {
        int s0 = g_bucket[base + i];
        float w0 = g_dinv[s0];
        uint2 v0 = xsv[(size_t)s0 * 32 + lane];
        float2 p01 = __half22float2(*(__half2*)&v0.x);
        float2 p23 = __half22float2(*(__half2*)&v0.y);
        a0 = fmaf(w0, p01.x, a0); a1 = fmaf(w0, p01.y, a1);
        a2 = fmaf(w0, p23.x, a2); a3 = fmaf(w0, p23.y, a3);
    }
    a0 += c0; a1 += c1; a2 += c2; a3 += c3;

    float4 bb = ((const float4*)b)[lane];
    float4 o;
    o.x = fmaxf(fmaf(w_self, a0, bb.x), 0.f);
    o.y = fmaxf(fmaf(w_self, a1, bb.y), 0.f);
    o.z = fmaxf(fmaf(w_self, a2, bb.z), 0.f);
    o.w = fmaxf(fmaf(w_self, a3, bb.w), 0.f);
    ((float4*)out)[(size_t)gw * 32 + lane] = o;
}

// ---------------------------------------------------------------- launcher
extern "C" void kernel_launch(void* const* d_in, const int* in_sizes, int n_in,
                              void* d_out, int out_size) {
    const float* x  = (const float*)d_in[0];
    const void*  ei = d_in[1];                 // int32 or int64, auto-detected
    const float* W  = (const float*)d_in[2];
    const float* b  = (const float*)d_in[3];
    float* out      = (float*)d_out;

    int N = in_sizes[0] / HID;     // 100000
    int E = in_sizes[1] / 2;       // 1600000

    static int inited = 0;
    if (!inited) {
        cudaFuncSetAttribute(k_gemm, cudaFuncAttributeMaxDynamicSharedMemorySize,
                             SM_TOTAL);
        inited = 1;
    }

    // single stream — no overlap exists anyway (all kernels fill the chip)
    k_fill_bucket<<<(E / 2 + 255) / 256, 256>>>(ei, E);
    k_dinv<<<(N + 255) / 256, 256>>>(N);
    k_gemm<<<(N + 127) / 128, 256, SM_TOTAL>>>(x, W, N);
    k_agg<<<(N * 32 + 255) / 256, 256>>>(b, out, N);
}